// round 4
// baseline (speedup 1.0000x reference)
#include <cuda_runtime.h>

#define B_ 4
#define N_ 128
#define L_ 20
#define D_ 512
#define KR (B_*L_)            // 80
#define SCALE 0.044194173824159216f   // 1/sqrt(512)

// ---- scratch (no allocation allowed) ----
__device__ float g_Gpart[4*D_*D_];    // K-split partials of G = Wk^T @ Wq
__device__ float g_G[D_*D_];          // G reduced
__device__ float g_rtp[4*KR*D_];      // K-split partials of Rt = f_w @ G
__device__ float g_c2[KR];            // c2[l] = (Wk^T bq) . f_w[l]
__device__ float g_fbq[B_*N_*D_];     // gated boundary features
__device__ float g_Ab[B_*N_*N_];      // boundary self-attention
__device__ float g_part[B_*4*N_*N_];  // K-split partials of score GEMM

// ============================================================
// Generic fp32 K-split partial GEMM, now with TRANSA.
// logical A[r][k] = TRANSA ? Araw[k*lda + r] : Araw[r*lda + k]
// TRANSB:  C[r][c] = sum_k A[r][k]*B[c*ldB + k]
// !TRANSB: C[r][c] = sum_k A[r][k]*B[k*ldB + c]
// Tile 16x128, 128 threads, 4x4 micro-tile, KC=16.
// ============================================================
template<bool TRANSA, bool TRANSB>
__global__ void __launch_bounds__(128)
gemm_part(const float* __restrict__ A, const float* __restrict__ B,
          float* __restrict__ Cpart, int M, int Ncol, int K, int lda, int ldB,
          int nsplit, int strideA, int strideB)
{
    const int TM = 16, TN = 128, KC = 16;
    int batch = blockIdx.z / nsplit;
    int split = blockIdx.z - batch * nsplit;
    int klen  = K / nsplit;
    int kbase = split * klen;
    A += (long)batch * strideA;
    B += (long)batch * strideB;
    float* C = Cpart + (long)(batch * nsplit + split) * M * Ncol;

    __shared__ float As[KC][TM];
    __shared__ float Bs[KC][TN];

    int row0 = blockIdx.x * TM;
    int col0 = blockIdx.y * TN;
    int tid = threadIdx.x;
    int tr = tid >> 5;      // 0..3
    int tc = tid & 31;      // 0..31

    float acc[4][4];
    #pragma unroll
    for (int i = 0; i < 4; i++)
        #pragma unroll
        for (int j = 0; j < 4; j++) acc[i][j] = 0.f;

    for (int kb = 0; kb < klen; kb += KC) {
        int k0 = kbase + kb;
        if (TRANSA) {
            // As[kc][r] = Araw[(k0+kc)*lda + row0 + r]
            int kc = tid >> 3, r2 = (tid & 7) * 2;
            float2 av = *(const float2*)(A + (long)(k0 + kc) * lda + row0 + r2);
            As[kc][r2]     = av.x;
            As[kc][r2 + 1] = av.y;
        } else {
            int idx = tid * 2;
            int r = idx >> 4, kc = idx & 15;
            float2 av = *(const float2*)(A + (long)(row0 + r) * lda + k0 + kc);
            As[kc][r]     = av.x;
            As[kc + 1][r] = av.y;
        }
        if (TRANSB) {
            const float* bp = B + (long)(col0 + tid) * ldB + k0;
            #pragma unroll
            for (int q = 0; q < 4; q++) {
                float4 v = *(const float4*)(bp + q * 4);
                Bs[q*4+0][tid] = v.x; Bs[q*4+1][tid] = v.y;
                Bs[q*4+2][tid] = v.z; Bs[q*4+3][tid] = v.w;
            }
        } else {
            #pragma unroll
            for (int p = 0; p < 4; p++) {
                int kc = (tid >> 5) + p * 4;
                int c4 = (tid & 31) * 4;
                float4 v = *(const float4*)(B + (long)(k0 + kc) * ldB + col0 + c4);
                *(float4*)&Bs[kc][c4] = v;
            }
        }
        __syncthreads();
        #pragma unroll
        for (int kc = 0; kc < KC; kc++) {
            float4 a4 = ((const float4*)As[kc])[tr];
            float4 b4 = ((const float4*)Bs[kc])[tc];
            acc[0][0] += a4.x*b4.x; acc[0][1] += a4.x*b4.y; acc[0][2] += a4.x*b4.z; acc[0][3] += a4.x*b4.w;
            acc[1][0] += a4.y*b4.x; acc[1][1] += a4.y*b4.y; acc[1][2] += a4.y*b4.z; acc[1][3] += a4.y*b4.w;
            acc[2][0] += a4.z*b4.x; acc[2][1] += a4.z*b4.y; acc[2][2] += a4.z*b4.z; acc[2][3] += a4.z*b4.w;
            acc[3][0] += a4.w*b4.x; acc[3][1] += a4.w*b4.y; acc[3][2] += a4.w*b4.z; acc[3][3] += a4.w*b4.w;
        }
        __syncthreads();
    }
    #pragma unroll
    for (int i = 0; i < 4; i++) {
        int row = row0 + tr * 4 + i;
        float4 v = make_float4(acc[i][0], acc[i][1], acc[i][2], acc[i][3]);
        *(float4*)(C + (long)row * Ncol + col0 + tc * 4) = v;
    }
}

// Blocks 0..127: G = sum of 4 K-split partials (float4).
// Block 128:     u = bq^T @ Wk, then c2[l] = u . f_w[l]   (80 rows)
__global__ void __launch_bounds__(512)
reduce_G_kernel(const float* __restrict__ Wk, const float* __restrict__ bq,
                const float* __restrict__ f_w)
{
    if (blockIdx.x < 128) {
        const int S = D_*D_/4;   // 65536 float4
        int i = blockIdx.x * 512 + threadIdx.x;
        const float4* p = (const float4*)g_Gpart;
        float4 a = p[i], b = p[S + i], c = p[2*S + i], e = p[3*S + i];
        ((float4*)g_G)[i] = make_float4(a.x+b.x+c.x+e.x, a.y+b.y+c.y+e.y,
                                        a.z+b.z+c.z+e.z, a.w+b.w+c.w+e.w);
    } else {
        __shared__ float su[D_];
        int e = threadIdx.x;
        float u = 0.f;
        #pragma unroll 8
        for (int d = 0; d < D_; d++) u = fmaf(bq[d], Wk[d*D_ + e], u);
        su[e] = u;
        __syncthreads();
        int w = e >> 5, lane = e & 31;
        for (int l = w; l < KR; l += 16) {
            const float* fr = f_w + l * D_;
            float p = 0.f;
            #pragma unroll
            for (int x = lane; x < D_; x += 32) p += su[x] * fr[x];
            #pragma unroll
            for (int off = 16; off > 0; off >>= 1) p += __shfl_xor_sync(0xffffffffu, p, off);
            if (lane == 0) g_c2[l] = p;
        }
    }
}

// cross-attention: scores[n,l] = f_b[n].Rt[l] + c2[l] (softmax-equivalent),
// softmax over l, then f_bq = f_b * (attn@f_w + f_s).
// Rt partials summed inline (no reduce kernel).
__global__ void __launch_bounds__(256) attn_kernel(const float* __restrict__ f_b,
                                                   const float* __restrict__ f_w,
                                                   const float* __restrict__ f_s)
{
    int bn = blockIdx.x; int b = bn >> 7;
    __shared__ float fb[D_];
    __shared__ float sl[L_];
    int tid = threadIdx.x;
    fb[tid]       = f_b[bn*D_ + tid];
    fb[tid + 256] = f_b[bn*D_ + tid + 256];
    __syncthreads();
    int w = tid >> 5, lane = tid & 31;
    for (int l = w; l < L_; l += 8) {
        const float* r0 = g_rtp + (b*L_ + l) * D_;
        float p = 0.f;
        #pragma unroll
        for (int e = lane; e < D_; e += 32) {
            float rt = r0[e] + r0[KR*D_ + e] + r0[2*KR*D_ + e] + r0[3*KR*D_ + e];
            p = fmaf(fb[e], rt, p);
        }
        #pragma unroll
        for (int off = 16; off > 0; off >>= 1) p += __shfl_xor_sync(0xffffffffu, p, off);
        if (lane == 0) sl[l] = (p + g_c2[b*L_ + l]) * SCALE;
    }
    __syncthreads();
    if (tid == 0) {
        float mx = sl[0];
        #pragma unroll
        for (int l = 1; l < L_; l++) mx = fmaxf(mx, sl[l]);
        float s = 0.f;
        #pragma unroll
        for (int l = 0; l < L_; l++) { float e = __expf(sl[l] - mx); sl[l] = e; s += e; }
        float inv = __fdividef(1.f, s);
        #pragma unroll
        for (int l = 0; l < L_; l++) sl[l] *= inv;
    }
    __syncthreads();
    for (int d = tid; d < D_; d += 256) {
        float acc = 0.f;
        #pragma unroll
        for (int l = 0; l < L_; l++) acc += sl[l] * f_w[(b*L_ + l)*D_ + d];
        g_fbq[bn*D_ + d] = fb[d] * (acc + f_s[b*D_ + d]);
    }
}

// sum score partials, scale, row softmax -> A_b
__global__ void __launch_bounds__(128) score_softmax()
{
    int bn = blockIdx.x; int b = bn >> 7; int n = bn & 127;
    int m = threadIdx.x;
    float s = 0.f;
    #pragma unroll
    for (int sp = 0; sp < 4; sp++) s += g_part[(((b*4 + sp)*N_) + n)*N_ + m];
    s *= SCALE;
    __shared__ float red[4];
    float mx = s;
    #pragma unroll
    for (int off = 16; off > 0; off >>= 1) mx = fmaxf(mx, __shfl_xor_sync(0xffffffffu, mx, off));
    if ((m & 31) == 0) red[m >> 5] = mx;
    __syncthreads();
    mx = fmaxf(fmaxf(red[0], red[1]), fmaxf(red[2], red[3]));
    float e = __expf(s - mx);
    __syncthreads();
    float sm = e;
    #pragma unroll
    for (int off = 16; off > 0; off >>= 1) sm += __shfl_xor_sync(0xffffffffu, sm, off);
    if ((m & 31) == 0) red[m >> 5] = sm;
    __syncthreads();
    sm = red[0] + red[1] + red[2] + red[3];
    g_Ab[bn*N_ + m] = e * __fdividef(1.f, sm);
}

// out = f_b  (init for the atomic accumulation)
__global__ void __launch_bounds__(512) init_out(const float* __restrict__ f_b,
                                                float* __restrict__ out)
{
    int i = blockIdx.x * 512 + threadIdx.x;   // 65536 float4
    ((float4*)out)[i] = ((const float4*)f_b)[i];
}

// sigmoid(x) = 0.5*tanh(0.5x)+0.5 — 1 MUFU instead of 2
__device__ __forceinline__ float sigmoid_fast(float x)
{
    float t;
    asm("tanh.approx.f32 %0, %1;" : "=f"(t) : "f"(0.5f * x));
    return fmaf(0.5f, t, 0.5f);
}

// f_m streaming kernel, m-split x4, 4-j grouping; RED.ADD directly into out.
__global__ void __launch_bounds__(512) final_split(const float* __restrict__ f_b,
                                                   const float* __restrict__ f_s,
                                                   const float* __restrict__ f_m,
                                                   float* __restrict__ out)
{
    int bidx  = blockIdx.x;          // 0..511
    int split = bidx & 3;
    int jg    = (bidx >> 2) & 31;
    int b     = bidx >> 7;
    int j0    = jg * 4;
    int m0    = split * 32;
    int d     = threadIdx.x;

    __shared__ float2 a2[4][32];     // {A_b[b][j][m], A_b[b][m][j]} for this m-chunk
    if (d < 128) {
        int jj = d >> 5, m = d & 31;
        a2[jj][m] = make_float2(g_Ab[(b*N_ + j0 + jj)*N_ + m0 + m],
                                g_Ab[(b*N_ + m0 + m)*N_ + j0 + jj]);
    }
    __syncthreads();

    float fsd = f_s[b*D_ + d];
    float acc[4] = {0.f, 0.f, 0.f, 0.f};
    const float* fmp = f_m + (((long)(b*N_ + m0))*N_ + j0)*D_ + d;
    const float* fbp = f_b + (b*N_ + m0)*D_ + d;

    #pragma unroll 4
    for (int m = 0; m < 32; m++) {
        float fbv = fbp[m*D_];
        #pragma unroll
        for (int jj = 0; jj < 4; jj++) {
            float x = fmp[(long)m*(N_*D_) + jj*D_];
            float2 a = a2[jj][m];
            float sg = sigmoid_fast(x * fsd);
            acc[jj] = fmaf(a.x, fbv, acc[jj]);
            acc[jj] = fmaf(a.y * sg, x, acc[jj]);
        }
    }
    #pragma unroll
    for (int jj = 0; jj < 4; jj++)
        atomicAdd(out + ((b*N_ + j0 + jj)*D_ + d), acc[jj]);
}

extern "C" void kernel_launch(void* const* d_in, const int* in_sizes, int n_in,
                              void* d_out, int out_size)
{
    const float* f_b = (const float*)d_in[0];
    const float* f_w = (const float*)d_in[1];
    const float* f_s = (const float*)d_in[2];
    const float* f_m = (const float*)d_in[3];
    const float* Wq  = (const float*)d_in[4];
    const float* bq  = (const float*)d_in[5];
    const float* Wk  = (const float*)d_in[6];
    const float* bk  = (const float*)d_in[7];   // unused: cancels in softmax
    (void)bk;
    float* out = (float*)d_out;

    void *p_Gpart, *p_G, *p_rtp, *p_fbq, *p_part;
    cudaGetSymbolAddress(&p_Gpart, g_Gpart);
    cudaGetSymbolAddress(&p_G,     g_G);
    cudaGetSymbolAddress(&p_rtp,   g_rtp);
    cudaGetSymbolAddress(&p_fbq,   g_fbq);
    cudaGetSymbolAddress(&p_part,  g_part);

    // 0) out = f_b (enables RED.ADD accumulation in final_split)
    init_out<<<128, 512>>>(f_b, out);
    // 1) G = Wk^T @ Wq   (TN GEMM, K-split 4, 512 blocks — fills the chip)
    gemm_part<true, false><<<dim3(32, 4, 4), 128>>>(Wk, Wq, (float*)p_Gpart,
                                                    D_, D_, D_, D_, D_, 4, 0, 0);
    // 2) reduce G; compute u = bq^T Wk and c2 = f_w @ u
    reduce_G_kernel<<<129, 512>>>(Wk, bq, f_w);
    // 3) Rt partials = f_w @ G (NN, K-split 4) — partials summed inside attn
    gemm_part<false, false><<<dim3(5, 4, 4), 128>>>(f_w, (const float*)p_G,
                                                    (float*)p_rtp, KR, D_, D_, D_, D_, 4, 0, 0);
    // 4) cross-attn softmax + gating -> f_bq
    attn_kernel<<<B_*N_, 256>>>(f_b, f_w, f_s);
    // 5) self-attn score partials per batch (NT, batched, K-split 4)
    gemm_part<false, true><<<dim3(8, 1, 16), 128>>>((const float*)p_fbq, (const float*)p_fbq,
                                                    (float*)p_part, N_, N_, D_, D_, D_, 4,
                                                    N_*D_, N_*D_);
    score_softmax<<<B_*N_, 128>>>();
    // 6) DRAM-bound f_m stream, m-split x4, atomic accumulate into out
    final_split<<<512, 512>>>(f_b, f_s, f_m, out);
}

// round 5
// speedup vs baseline: 1.2160x; 1.2160x over previous
#include <cuda_runtime.h>

#define B_ 4
#define N_ 128
#define L_ 20
#define D_ 512
#define KR (B_*L_)            // 80
#define SCALE 0.044194173824159216f   // 1/sqrt(512)

// ---- scratch (no allocation allowed) ----
__device__ float g_k[KR*D_];          // k  = f_w @ Wk^T + bk
__device__ float g_kk[KR*D_];         // kk = k @ Wq
__device__ float g_c[KR];             // c[l] = bq . k[l]
__device__ float g_fbq[B_*N_*D_];     // gated boundary features
__device__ float g_Ab[B_*N_*N_];      // boundary self-attention

// ============================================================
// Small-GEMM, no K-split: C[80,512] tile TM=8 x TN=32, 128 thr.
// TRANSB:  C[r][c] = sum_k A[r][k]*B[c*512+k]   (B rows = K-major)
// !TRANSB: C[r][c] = sum_k A[r][k]*B[k*512+c]
// BIAS: += bias[c].  CEPI (blockIdx.y==0): cvec[r] = bq . A[r].
// ============================================================
template<bool TRANSB, bool BIAS, bool CEPI>
__global__ void __launch_bounds__(128)
gemm8(const float* __restrict__ A, const float* __restrict__ Bm,
      const float* __restrict__ bias, const float* __restrict__ bqv,
      float* __restrict__ C, float* __restrict__ cvec)
{
    const int Kd = D_, Nd = D_;
    int row0 = blockIdx.x * 8;     // gridx = 10
    int col0 = blockIdx.y * 32;    // gridy = 16

    __shared__ float As[8][33];
    __shared__ float Bs[32][36];

    int t = threadIdx.x;
    int c  = t & 31;
    int rh = t >> 5;               // 0..3 -> rows rh*2, rh*2+1

    float acc0 = 0.f, acc1 = 0.f;

    for (int k0 = 0; k0 < Kd; k0 += 32) {
        // A tile: 8 rows x 32 k (256 elems, 2/thread, coalesced over k)
        {
            int kc = t & 31, r2 = (t >> 5) * 2;
            As[r2][kc]     = A[(row0 + r2) * Kd + k0 + kc];
            As[r2 + 1][kc] = A[(row0 + r2 + 1) * Kd + k0 + kc];
        }
        if (TRANSB) {
            // Bs[kc][cc] = Bm[(col0+cc)*Kd + k0+kc]; thread: cc=t>>2, 2 float4
            int cc = t >> 2, h = t & 3;
            const float4* bp = (const float4*)(Bm + (long)(col0 + cc) * Kd + k0 + h * 8);
            #pragma unroll
            for (int q = 0; q < 2; q++) {
                float4 v = bp[q];
                int kc = h * 8 + q * 4;
                Bs[kc][cc] = v.x; Bs[kc+1][cc] = v.y; Bs[kc+2][cc] = v.z; Bs[kc+3][cc] = v.w;
            }
        } else {
            // Bs[kc][c4] = Bm[(k0+kc)*Nd + col0+c4]
            #pragma unroll
            for (int p = 0; p < 2; p++) {
                int kc = (t >> 3) + p * 16;
                int c4 = (t & 7) * 4;
                float4 v = *(const float4*)(Bm + (long)(k0 + kc) * Nd + col0 + c4);
                Bs[kc][c4] = v.x; Bs[kc][c4+1] = v.y; Bs[kc][c4+2] = v.z; Bs[kc][c4+3] = v.w;
            }
        }
        __syncthreads();
        #pragma unroll
        for (int kc = 0; kc < 32; kc++) {
            float bv = Bs[kc][c];
            acc0 = fmaf(As[rh*2][kc],     bv, acc0);
            acc1 = fmaf(As[rh*2 + 1][kc], bv, acc1);
        }
        __syncthreads();
    }
    float bb = BIAS ? bias[col0 + c] : 0.f;
    C[(row0 + rh*2)     * Nd + col0 + c] = acc0 + bb;
    C[(row0 + rh*2 + 1) * Nd + col0 + c] = acc1 + bb;

    if (CEPI && blockIdx.y == 0) {
        __shared__ float cred[8][17];
        int r = t >> 4, seg = t & 15;
        float s = 0.f;
        const float4* kr  = (const float4*)(A + (long)(row0 + r) * Kd + seg * 32);
        const float4* bq4 = (const float4*)(bqv + seg * 32);
        #pragma unroll
        for (int q = 0; q < 8; q++) {
            float4 kv = kr[q], bv = bq4[q];
            s += kv.x*bv.x + kv.y*bv.y + kv.z*bv.z + kv.w*bv.w;
        }
        cred[r][seg] = s;
        __syncthreads();
        if (t < 8) {
            float tot = 0.f;
            #pragma unroll
            for (int q = 0; q < 16; q++) tot += cred[t][q];
            cvec[row0 + t] = tot;
        }
    }
}

// cross-attention (L=20) + sentence gating -> f_bq ; also out = f_b (init)
__global__ void __launch_bounds__(256) attn_kernel(const float* __restrict__ f_b,
                                                   const float* __restrict__ f_w,
                                                   const float* __restrict__ f_s,
                                                   float* __restrict__ out)
{
    int bn = blockIdx.x; int b = bn >> 7;
    __shared__ float fb[D_];
    __shared__ float sl[L_];
    int tid = threadIdx.x;
    fb[tid]       = f_b[bn*D_ + tid];
    fb[tid + 256] = f_b[bn*D_ + tid + 256];
    __syncthreads();
    int w = tid >> 5, lane = tid & 31;
    for (int l = w; l < L_; l += 8) {
        const float* kr = g_kk + (b*L_ + l) * D_;
        float p = 0.f;
        #pragma unroll
        for (int e = lane; e < D_; e += 32) p = fmaf(fb[e], kr[e], p);
        #pragma unroll
        for (int off = 16; off > 0; off >>= 1) p += __shfl_xor_sync(0xffffffffu, p, off);
        if (lane == 0) sl[l] = (p + g_c[b*L_ + l]) * SCALE;
    }
    __syncthreads();
    if (tid == 0) {
        float mx = sl[0];
        #pragma unroll
        for (int l = 1; l < L_; l++) mx = fmaxf(mx, sl[l]);
        float s = 0.f;
        #pragma unroll
        for (int l = 0; l < L_; l++) { float e = __expf(sl[l] - mx); sl[l] = e; s += e; }
        float inv = __fdividef(1.f, s);
        #pragma unroll
        for (int l = 0; l < L_; l++) sl[l] *= inv;
    }
    __syncthreads();
    for (int d = tid; d < D_; d += 256) {
        float acc = 0.f;
        #pragma unroll
        for (int l = 0; l < L_; l++) acc += sl[l] * f_w[(b*L_ + l)*D_ + d];
        g_fbq[bn*D_ + d] = fb[d] * (acc + f_s[b*D_ + d]);
        out[bn*D_ + d] = fb[d];          // init residual for final RED.ADD
    }
}

// ============================================================
// Fused score GEMM + row softmax.
// Block: 4 score rows x full 128 cols (row complete -> softmax in-block).
// grid (32 row-tiles, 4 batches), 256 threads.
// ============================================================
__global__ void __launch_bounds__(256) score_softmax_f()
{
    int b = blockIdx.y;
    int row0 = blockIdx.x * 4;
    const float* Abase = g_fbq + (long)b * N_ * D_;

    __shared__ float As[4][33];
    __shared__ float Bs[32][132];
    __shared__ float Ssc[4][128];

    int t = threadIdx.x;
    int c  = t & 127;
    int rh = t >> 7;          // 0..1 -> rows rh*2, rh*2+1

    float acc0 = 0.f, acc1 = 0.f;

    for (int k0 = 0; k0 < D_; k0 += 32) {
        if (t < 128) {
            int kc = t & 31, r = t >> 5;     // 4 rows
            As[r][kc] = Abase[(row0 + r) * D_ + k0 + kc];
        }
        {
            int cc = t >> 1, h = t & 1;
            const float4* bp = (const float4*)(Abase + (long)cc * D_ + k0 + h * 16);
            #pragma unroll
            for (int q = 0; q < 4; q++) {
                float4 v = bp[q];
                int kc = h * 16 + q * 4;
                Bs[kc][cc] = v.x; Bs[kc+1][cc] = v.y; Bs[kc+2][cc] = v.z; Bs[kc+3][cc] = v.w;
            }
        }
        __syncthreads();
        #pragma unroll
        for (int kc = 0; kc < 32; kc++) {
            float bv = Bs[kc][c];
            acc0 = fmaf(As[rh*2][kc],     bv, acc0);
            acc1 = fmaf(As[rh*2 + 1][kc], bv, acc1);
        }
        __syncthreads();
    }
    Ssc[rh*2][c]     = acc0 * SCALE;
    Ssc[rh*2 + 1][c] = acc1 * SCALE;
    __syncthreads();

    int w = t >> 5, lane = t & 31;
    if (w < 4) {
        float4 v = *(const float4*)&Ssc[w][lane * 4];
        float mx = fmaxf(fmaxf(v.x, v.y), fmaxf(v.z, v.w));
        #pragma unroll
        for (int off = 16; off > 0; off >>= 1) mx = fmaxf(mx, __shfl_xor_sync(0xffffffffu, mx, off));
        float e0 = __expf(v.x - mx), e1 = __expf(v.y - mx);
        float e2 = __expf(v.z - mx), e3 = __expf(v.w - mx);
        float s = e0 + e1 + e2 + e3;
        #pragma unroll
        for (int off = 16; off > 0; off >>= 1) s += __shfl_xor_sync(0xffffffffu, s, off);
        float inv = __fdividef(1.f, s);
        *(float4*)&g_Ab[((long)b*N_ + row0 + w) * N_ + lane * 4] =
            make_float4(e0*inv, e1*inv, e2*inv, e3*inv);
    }
}

// sigmoid(x) = 0.5*tanh(0.5x)+0.5 — 1 MUFU instead of 2
__device__ __forceinline__ float sigmoid_fast(float x)
{
    float t;
    asm("tanh.approx.f32 %0, %1;" : "=f"(t) : "f"(0.5f * x));
    return fmaf(0.5f, t, 0.5f);
}

// f_m streaming kernel, m-split x4; RED.ADD directly into out (out pre-inited to f_b).
__global__ void __launch_bounds__(512) final_split(const float* __restrict__ f_b,
                                                   const float* __restrict__ f_s,
                                                   const float* __restrict__ f_m,
                                                   float* __restrict__ out)
{
    int bidx  = blockIdx.x;          // 0..511
    int split = bidx & 3;
    int jg    = (bidx >> 2) & 31;
    int b     = bidx >> 7;
    int j0    = jg * 4;
    int m0    = split * 32;
    int d     = threadIdx.x;

    __shared__ float2 a2[4][32];     // {A_b[b][j][m], A_b[b][m][j]} for this m-chunk
    if (d < 128) {
        int jj = d >> 5, m = d & 31;
        a2[jj][m] = make_float2(g_Ab[(b*N_ + j0 + jj)*N_ + m0 + m],
                                g_Ab[(b*N_ + m0 + m)*N_ + j0 + jj]);
    }
    __syncthreads();

    float fsd = f_s[b*D_ + d];
    float acc[4] = {0.f, 0.f, 0.f, 0.f};
    const float* fmp = f_m + (((long)(b*N_ + m0))*N_ + j0)*D_ + d;
    const float* fbp = f_b + (b*N_ + m0)*D_ + d;

    #pragma unroll 4
    for (int m = 0; m < 32; m++) {
        float fbv = fbp[m*D_];
        #pragma unroll
        for (int jj = 0; jj < 4; jj++) {
            float x = fmp[(long)m*(N_*D_) + jj*D_];
            float2 a = a2[jj][m];
            float sg = sigmoid_fast(x * fsd);
            acc[jj] = fmaf(a.x, fbv, acc[jj]);
            acc[jj] = fmaf(a.y * sg, x, acc[jj]);
        }
    }
    #pragma unroll
    for (int jj = 0; jj < 4; jj++)
        atomicAdd(out + ((b*N_ + j0 + jj)*D_ + d), acc[jj]);
}

extern "C" void kernel_launch(void* const* d_in, const int* in_sizes, int n_in,
                              void* d_out, int out_size)
{
    const float* f_b = (const float*)d_in[0];
    const float* f_w = (const float*)d_in[1];
    const float* f_s = (const float*)d_in[2];
    const float* f_m = (const float*)d_in[3];
    const float* Wq  = (const float*)d_in[4];
    const float* bq  = (const float*)d_in[5];
    const float* Wk  = (const float*)d_in[6];
    const float* bk  = (const float*)d_in[7];
    float* out = (float*)d_out;

    void *p_k, *p_kk, *p_c;
    cudaGetSymbolAddress(&p_k,  g_k);
    cudaGetSymbolAddress(&p_kk, g_kk);
    cudaGetSymbolAddress(&p_c,  g_c);

    // 1) k = f_w @ Wk^T + bk            (TRANSB, bias)
    gemm8<true, true, false><<<dim3(10, 16), 128>>>(f_w, Wk, bk, nullptr,
                                                    (float*)p_k, nullptr);
    // 2) kk = k @ Wq ; c = bq . k       (NN, c-epilogue)
    gemm8<false, false, true><<<dim3(10, 16), 128>>>((const float*)p_k, Wq, nullptr, bq,
                                                     (float*)p_kk, (float*)p_c);
    // 3) cross-attn softmax + gating -> f_bq ; out = f_b
    attn_kernel<<<B_*N_, 256>>>(f_b, f_w, f_s, out);
    // 4) fused self-attn score GEMM + softmax -> A_b
    score_softmax_f<<<dim3(32, 4), 256>>>();
    // 5) DRAM-bound f_m stream, m-split x4, RED.ADD into out
    final_split<<<512, 512>>>(f_b, f_s, f_m, out);
}